// round 12
// baseline (speedup 1.0000x reference)
#include <cuda_runtime.h>
#include <cuda_fp16.h>
#include <math.h>
#include <stdint.h>

// ---------------- model constants ----------------
#define L_     2
#define HID_   4096
#define NH_    32
#define HD_    128
#define INTER_ 13696
#define B_     2
#define S_     1024
#define T_     2048
#define NBLK_  160
#define BLK_   16
#define ROT_   64
#define NFREQ_ 32
#define EPS_   1e-5f
#define SCALE_ 0.08838834764831845f

// ---------------- scratch ----------------
#define OFF_H      ((size_t)0)
#define OFF_RES    ((size_t)8388608)
#define OFF_NORM   ((size_t)16777216)   // half planes: normh/norml
#define OFF_Q      ((size_t)25165824)
#define OFF_K      ((size_t)33554432)
#define OFF_V      ((size_t)41943040)
#define OFF_O      ((size_t)50331648)   // half planes: oh/ol
#define OFF_ATTN   ((size_t)58720256)
#define OFF_QKV    ((size_t)67108864)
#define OFF_SCORES ((size_t)92274688)
#define OFF_GU     ((size_t)159383552)
#define OFF_ACT    ((size_t)215482368)  // half planes: acth/actl (exact fit)
#define OFF_WPH    ((size_t)243531776)  // packed weight hi plane (u32 slots)
#define OFF_WPL    (OFF_WPH + (size_t)56098816)
#define SCRATCH_TOTAL (OFF_WPL + (size_t)56098816)

__device__ float g_scratch[SCRATCH_TOTAL];

__device__ __forceinline__ void split2_f16(float x0, float x1,
                                           uint32_t& hi, uint32_t& lo) {
    __half h0 = __float2half_rn(x0);
    __half h1 = __float2half_rn(x1);
    __half l0 = __float2half_rn(x0 - __half2float(h0));
    __half l1 = __float2half_rn(x1 - __half2float(h1));
    hi = (uint32_t)__half_as_ushort(h0) | ((uint32_t)__half_as_ushort(h1) << 16);
    lo = (uint32_t)__half_as_ushort(l0) | ((uint32_t)__half_as_ushort(l1) << 16);
}

__device__ __forceinline__ uint32_t s2u(const void* p) {
    return (uint32_t)__cvta_generic_to_shared(p);
}
#define CP16(dst, src) \
    asm volatile("cp.async.cg.shared.global [%0], [%1], 16;" :: "r"(dst), "l"(src) : "memory")
#define CP_COMMIT() asm volatile("cp.async.commit_group;" ::: "memory")
#define CP_WAIT1() asm volatile("cp.async.wait_group 1;" ::: "memory")
#define CP_WAIT0() asm volatile("cp.async.wait_group 0;" ::: "memory")

#define MMA_F16(ACC, A0, A1, A2, A3, B0, B1)                                   \
    asm volatile(                                                              \
        "mma.sync.aligned.m16n8k16.row.col.f32.f16.f16.f32 "                   \
        "{%0,%1,%2,%3}, {%4,%5,%6,%7}, {%8,%9}, {%0,%1,%2,%3};"                \
        : "+f"((ACC)[0]), "+f"((ACC)[1]), "+f"((ACC)[2]), "+f"((ACC)[3])       \
        : "r"(A0), "r"(A1), "r"(A2), "r"(A3), "r"(B0), "r"(B1))

// ---------------- embedding gather ----------------
__global__ void embed_kernel(const int* __restrict__ ids,
                             const float* __restrict__ E,
                             float* __restrict__ h) {
    int t = blockIdx.x;
    int id = ids[t];
    const float* er = E + (size_t)id * HID_;
    float* hr = h + (size_t)t * HID_;
    for (int i = threadIdx.x; i < HID_; i += 256) hr[i] = er[i];
}

// ---------------- fused (residual-add) RMSNorm; optional split-f16 out ----
__global__ void rmsnorm_kernel(const float* __restrict__ x,
                               const float* __restrict__ resin,
                               const float* __restrict__ w,
                               float* __restrict__ outn,
                               __half* __restrict__ outh,
                               __half* __restrict__ outl,
                               float* __restrict__ resout) {
    int t = blockIdx.x, tid = threadIdx.x;
    const float* xr = x + (size_t)t * HID_;
    const float* rr = resin ? resin + (size_t)t * HID_ : nullptr;

    float v[16];
    float ss = 0.f;
#pragma unroll
    for (int i = 0; i < 16; i++) {
        int c = tid + i * 256;
        float a = xr[c];
        if (rr) a += rr[c];
        v[i] = a;
        ss += a * a;
    }
    __shared__ float red[8];
#pragma unroll
    for (int o = 16; o; o >>= 1) ss += __shfl_xor_sync(0xffffffffu, ss, o);
    if ((tid & 31) == 0) red[tid >> 5] = ss;
    __syncthreads();
    float tot = 0.f;
#pragma unroll
    for (int i = 0; i < 8; i++) tot += red[i];
    float inv = rsqrtf(tot * (1.0f / HID_) + EPS_);
#pragma unroll
    for (int i = 0; i < 16; i++) {
        int c = tid + i * 256;
        size_t o = (size_t)t * HID_ + c;
        if (resout) resout[o] = v[i];
        float y = w[c] * v[i] * inv;
        if (outn) outn[o] = y;
        if (outh) {
            __half h = __float2half_rn(y);
            outh[o] = h;
            outl[o] = __float2half_rn(y - __half2float(h));
        }
    }
}

// ---------------- weight pack: W[K,N] fp32 -> hi/lo u32 planes [K/2][N] ---
__global__ void pack_w(const float* __restrict__ W,
                       uint32_t* __restrict__ Wh, uint32_t* __restrict__ Wl,
                       int N) {
    size_t idx = (size_t)blockIdx.x * 256 + threadIdx.x;
    size_t p = idx / N;
    size_t n = idx - p * N;
    float x0 = W[(2 * p) * N + n];
    float x1 = W[(2 * p + 1) * N + n];
    uint32_t h, l;
    split2_f16(x0, x1, h, l);
    Wh[idx] = h;
    Wl[idx] = l;
}

// ============================================================
// FP16x3 weight GEMM, occupancy-optimized: CTA 128x64, warp tile
// 32x32 (8 warps, 4x2), k-tile 16, 2-stage cp.async pipeline with
// wait_group 1 (R9 scheme). 3 CTAs/SM target (<=84 regs).
// Stage: AsH 6144 | AsL 6144 | BsH 4352 | BsL 4352 = 20992 B.
// ============================================================
#define WST 20992

__global__ void __launch_bounds__(256, 3) gemm_w(
    const __half* __restrict__ Ah, const __half* __restrict__ Al,
    const uint32_t* __restrict__ Bh, const uint32_t* __restrict__ Bl,
    const float* __restrict__ bias, float* __restrict__ C,
    int K, int N)
{
    extern __shared__ uint8_t sm[];
    int tid = threadIdx.x;
    int lane = tid & 31, warp = tid >> 5;
    int g = lane >> 2, tg = lane & 3;
    int wm = (warp >> 1) * 32, wn = (warp & 1) * 32;
    int m0 = blockIdx.y * 128, n0 = blockIdx.x * 64;

    // fill mapping: A 128 rows x 32B (16 halves) per plane
    int fr = tid >> 1;                  // 0..127 (A row)
    int fc = (tid & 1) * 16;            // byte chunk within 32B A row
    const __half* pah = Ah + (size_t)(m0 + fr) * K + (tid & 1) * 8;
    const __half* pal = Al + (size_t)(m0 + fr) * K + (tid & 1) * 8;
    // B: 8 k-pair rows x 64 u32; threads 0..127 fill both planes
    int bp = (tid & 127) >> 4;          // 0..7 (k-pair row)
    int bc = (tid & 15) * 4;            // u32 col 0..60
    const uint32_t* pbh = Bh + (size_t)bp * N + n0 + bc;
    const uint32_t* pbl = Bl + (size_t)bp * N + n0 + bc;

    auto fill = [&](int stage, int kt) {
        uint8_t* st = sm + stage * WST;
        int k0 = kt * 16;
        uint32_t da = s2u(st + fr * 48 + fc);
        CP16(da, pah + k0);
        CP16(da + 6144, pal + k0);
        if (tid < 128) {
            uint32_t db = s2u(st + 12288 + bp * 544 + bc * 4);
            size_t bo = (size_t)(k0 >> 1) * N;
            CP16(db, pbh + bo);
            CP16(db + 4352, pbl + bo);
        }
        CP_COMMIT();
    };

    float acc[2][4][4] = {};

    auto compute = [&](int stage) {
        const uint8_t* AsH = sm + stage * WST;
        const uint8_t* AsL = AsH + 6144;
        const uint8_t* BsH = AsH + 12288;
        const uint8_t* BsL = AsH + 16640;
        uint32_t ah[2][4], al[2][4];
#pragma unroll
        for (int mt = 0; mt < 2; mt++) {
            int m = wm + mt * 16 + g;
            const uint8_t* pH = AsH + m * 48 + tg * 4;
            const uint8_t* pL = AsL + m * 48 + tg * 4;
            ah[mt][0] = *(const uint32_t*)(pH);
            ah[mt][1] = *(const uint32_t*)(pH + 8 * 48);
            ah[mt][2] = *(const uint32_t*)(pH + 16);
            ah[mt][3] = *(const uint32_t*)(pH + 8 * 48 + 16);
            al[mt][0] = *(const uint32_t*)(pL);
            al[mt][1] = *(const uint32_t*)(pL + 8 * 48);
            al[mt][2] = *(const uint32_t*)(pL + 16);
            al[mt][3] = *(const uint32_t*)(pL + 8 * 48 + 16);
        }
#pragma unroll
        for (int nt = 0; nt < 4; nt++) {
            int n = wn + nt * 8 + g;
            const uint8_t* pH = BsH + tg * 544 + n * 4;
            const uint8_t* pL = BsL + tg * 544 + n * 4;
            uint32_t bh0 = *(const uint32_t*)(pH);
            uint32_t bh1 = *(const uint32_t*)(pH + 4 * 544);
            uint32_t bl0 = *(const uint32_t*)(pL);
            uint32_t bl1 = *(const uint32_t*)(pL + 4 * 544);
#pragma unroll
            for (int mt = 0; mt < 2; mt++) {
                MMA_F16(acc[mt][nt], ah[mt][0], ah[mt][1], ah[mt][2], ah[mt][3],
                        bl0, bl1);
                MMA_F16(acc[mt][nt], al[mt][0], al[mt][1], al[mt][2], al[mt][3],
                        bh0, bh1);
                MMA_F16(acc[mt][nt], ah[mt][0], ah[mt][1], ah[mt][2], ah[mt][3],
                        bh0, bh1);
            }
        }
    };

    int nk = K / 16;
    fill(0, 0);
    for (int kt = 0; kt < nk; kt++) {
        int buf = kt & 1;
        if (kt + 1 < nk) {
            fill(buf ^ 1, kt + 1);
            CP_WAIT1();
        } else {
            CP_WAIT0();
        }
        __syncthreads();
        compute(buf);
        __syncthreads();
    }

    // ---- epilogue ----
#pragma unroll
    for (int mt = 0; mt < 2; mt++) {
#pragma unroll
        for (int i = 0; i < 2; i++) {
            int r = m0 + wm + mt * 16 + g + i * 8;
#pragma unroll
            for (int nt = 0; nt < 4; nt++) {
                int c = n0 + wn + nt * 8 + 2 * tg;
                float v0 = acc[mt][nt][i * 2 + 0];
                float v1 = acc[mt][nt][i * 2 + 1];
                if (bias) {
                    v0 += bias[c];
                    v1 += bias[c + 1];
                }
                *(float2*)&C[(size_t)r * N + c] = make_float2(v0, v1);
            }
        }
    }
}

// ============================================================
// FP16x3 mma GEMM for attention (proven R9 structure).
// MODE 1: scores = scale * Q @ K^T (fp32 out, causal tile skip).
// MODE 2: O = P @ V, causal K-limit; writes split hi/lo fp16 planes.
// ============================================================
template<int MODE>
__global__ void __launch_bounds__(256) gemm_f16(
    const float* __restrict__ Ag, const float* __restrict__ Bg,
    float* __restrict__ Cf, __half* __restrict__ Ch, __half* __restrict__ Cl)
{
    int bx = blockIdx.x, by = blockIdx.y, bz = blockIdx.z;
    const float* A = Ag;
    const float* B = Bg;
    int K;
    size_t coff;
    if (MODE == 1) {
        if (bx > by) return;
        int b = bz >> 5, h = bz & 31;
        A += ((size_t)b * S_) * HID_ + h * HD_;
        B += ((size_t)b * S_) * HID_ + h * HD_;
        coff = (size_t)bz * S_ * S_;
        K = HD_;
    } else {
        int b = bz >> 5, h = bz & 31;
        A += (size_t)bz * S_ * S_;
        B += ((size_t)b * S_) * HID_ + h * HD_;
        coff = ((size_t)b * S_) * HID_ + h * HD_;
        K = (by + 1) * 128;
    }
    const int lda = (MODE == 1) ? HID_ : S_;
    const int ldb = HID_;

    __shared__ uint8_t AsH[2][6144], AsL[2][6144];
    __shared__ uint8_t BsH[2][6144], BsL[2][6144];

    int tid = threadIdx.x;
    int lane = tid & 31, warp = tid >> 5;
    int g = lane >> 2, tg = lane & 3;
    int wm = (warp & 1) * 64;
    int wn = (warp >> 1) * 32;

    int ar = tid >> 1;
    int ak = (tid & 1) * 8;
    const float* Aptr = A + (size_t)(by * 128 + ar) * lda + ak;

    const float* Bptr0;
    const float* Bptr1 = nullptr;
    int pk = 0, nq = 0;
    if (MODE == 1) {
        Bptr0 = B + (size_t)(bx * 128 + ar) * ldb + ak;
    } else {
        pk = tid >> 5;
        nq = (tid & 31) * 4;
        Bptr0 = B + (size_t)(2 * pk) * ldb + bx * 128 + nq;
        Bptr1 = Bptr0 + ldb;
    }

    float4 pa0, pa1, pb0, pb1;
    auto ldg_tile = [&](int k0) {
        pa0 = *(const float4*)(Aptr + k0);
        pa1 = *(const float4*)(Aptr + k0 + 4);
        if (MODE == 1) {
            pb0 = *(const float4*)(Bptr0 + k0);
            pb1 = *(const float4*)(Bptr0 + k0 + 4);
        } else {
            pb0 = *(const float4*)(Bptr0 + (size_t)k0 * ldb);
            pb1 = *(const float4*)(Bptr1 + (size_t)k0 * ldb);
        }
    };
    auto sts_tile = [&](int buf) {
        uint32_t h0, l0, h1, l1, h2, l2, h3, l3;
        split2_f16(pa0.x, pa0.y, h0, l0);
        split2_f16(pa0.z, pa0.w, h1, l1);
        split2_f16(pa1.x, pa1.y, h2, l2);
        split2_f16(pa1.z, pa1.w, h3, l3);
        *(uint4*)(AsH[buf] + ar * 48 + ak * 2) = make_uint4(h0, h1, h2, h3);
        *(uint4*)(AsL[buf] + ar * 48 + ak * 2) = make_uint4(l0, l1, l2, l3);
        if (MODE == 1) {
            split2_f16(pb0.x, pb0.y, h0, l0);
            split2_f16(pb0.z, pb0.w, h1, l1);
            split2_f16(pb1.x, pb1.y, h2, l2);
            split2_f16(pb1.z, pb1.w, h3, l3);
            *(uint4*)(BsH[buf] + ar * 48 + ak * 2) = make_uint4(h0, h1, h2, h3);
            *(uint4*)(BsL[buf] + ar * 48 + ak * 2) = make_uint4(l0, l1, l2, l3);
        } else {
            split2_f16(pb0.x, pb1.x, h0, l0);
            split2_f16(pb0.y, pb1.y, h1, l1);
            split2_f16(pb0.z, pb1.z, h2, l2);
            split2_f16(pb0.w, pb1.w, h3, l3);
            *(uint4*)(BsH[buf] + pk * 544 + nq * 4) = make_uint4(h0, h1, h2, h3);
            *(uint4*)(BsL[buf] + pk * 544 + nq * 4) = make_uint4(l0, l1, l2, l3);
        }
    };

    float acc[4][4][4] = {};

    auto compute = [&](int buf) {
        uint32_t ah[4][4], al[4][4], bh[4][2], bl[4][2];
#pragma unroll
        for (int mt = 0; mt < 4; mt++) {
            int m = wm + mt * 16 + g;
            const uint8_t* pH = AsH[buf] + m * 48 + tg * 4;
            const uint8_t* pL = AsL[buf] + m * 48 + tg * 4;
            ah[mt][0] = *(const uint32_t*)(pH);
            ah[mt][1] = *(const uint32_t*)(pH + 8 * 48);
            ah[mt][2] = *(const uint32_t*)(pH + 16);
            ah[mt][3] = *(const uint32_t*)(pH + 8 * 48 + 16);
            al[mt][0] = *(const uint32_t*)(pL);
            al[mt][1] = *(const uint32_t*)(pL + 8 * 48);
            al[mt][2] = *(const uint32_t*)(pL + 16);
            al[mt][3] = *(const uint32_t*)(pL + 8 * 48 + 16);
        }
#pragma unroll
        for (int nt = 0; nt < 4; nt++) {
            int n = wn + nt * 8 + g;
            if (MODE == 1) {
                const uint8_t* pH = BsH[buf] + n * 48 + tg * 4;
                const uint8_t* pL = BsL[buf] + n * 48 + tg * 4;
                bh[nt][0] = *(const uint32_t*)(pH);
                bh[nt][1] = *(const uint32_t*)(pH + 16);
                bl[nt][0] = *(const uint32_t*)(pL);
                bl[nt][1] = *(const uint32_t*)(pL + 16);
            } else {
                const uint8_t* pH = BsH[buf] + tg * 544 + n * 4;
                const uint8_t* pL = BsL[buf] + tg * 544 + n * 4;
                bh[nt][0] = *(const uint32_t*)(pH);
                bh[nt][1] = *(const uint32_t*)(pH + 4 * 544);
                bl[nt][0] = *(const uint32_t*)(pL);
                bl[nt][1] = *(const uint32_t*)(pL + 4 * 544);
            }
        }
#pragma unroll
        for (int mt = 0; mt < 4; mt++)
#pragma unroll
            for (int nt = 0; nt < 4; nt++) {
                MMA_F16(acc[mt][nt], ah[mt][0], ah[mt][1], ah[mt][2], ah[mt][3],
                        bl[nt][0], bl[nt][1]);
                MMA_F16(acc[mt][nt], al[mt][0], al[mt][1], al[mt][2], al[mt][3],
                        bh[nt][0], bh[nt][1]);
                MMA_F16(acc[mt][nt], ah[mt][0], ah[mt][1], ah[mt][2], ah[mt][3],
                        bh[nt][0], bh[nt][1]);
            }
    };

    int nk = K / 16;
    ldg_tile(0);
    sts_tile(0);
    __syncthreads();
    for (int kt = 0; kt < nk; kt++) {
        int buf = kt & 1;
        if (kt + 1 < nk) ldg_tile((kt + 1) * 16);
        compute(buf);
        if (kt + 1 < nk) sts_tile(buf ^ 1);
        __syncthreads();
    }

#pragma unroll
    for (int mt = 0; mt < 4; mt++) {
#pragma unroll
        for (int i = 0; i < 2; i++) {
            int r = by * 128 + wm + mt * 16 + g + i * 8;
#pragma unroll
            for (int nt = 0; nt < 4; nt++) {
                int c = bx * 128 + wn + nt * 8 + 2 * tg;
                float v0 = acc[mt][nt][i * 2 + 0];
                float v1 = acc[mt][nt][i * 2 + 1];
                if (MODE == 1) {
                    v0 *= SCALE_;
                    v1 *= SCALE_;
                    *(float2*)&Cf[coff + (size_t)r * S_ + c] =
                        make_float2(v0, v1);
                } else {
                    __half h0 = __float2half_rn(v0);
                    __half h1 = __float2half_rn(v1);
                    __half l0 = __float2half_rn(v0 - __half2float(h0));
                    __half l1 = __float2half_rn(v1 - __half2float(h1));
                    size_t o = coff + (size_t)r * HID_ + c;
                    *(half2*)&Ch[o] = make_half2(h0, h1);
                    *(half2*)&Cl[o] = make_half2(l0, l1);
                }
            }
        }
    }
}

// ---------------- rope + split + KV-cache scatter ----------------
__global__ void rope_scatter(const float* __restrict__ qkv,
                             const float* __restrict__ cosp,
                             const float* __restrict__ sinp,
                             const int* __restrict__ slots,
                             float* __restrict__ q, float* __restrict__ k,
                             float* __restrict__ v,
                             float* __restrict__ kc, float* __restrict__ vc) {
    int t = blockIdx.x, h = blockIdx.y, d = threadIdx.x;
    const float* row = qkv + (size_t)t * (3 * HID_);
    float qv, kv;
    if (d < ROT_) {
        int f = d >> 1;
        float c = cosp[t * NFREQ_ + f];
        float s = sinp[t * NFREQ_ + f];
        float q0 = row[h * HD_ + f * 2];
        float q1 = row[h * HD_ + f * 2 + 1];
        float k0 = row[HID_ + h * HD_ + f * 2];
        float k1 = row[HID_ + h * HD_ + f * 2 + 1];
        if (d & 1) { qv = q1 * c + q0 * s; kv = k1 * c + k0 * s; }
        else       { qv = q0 * c - q1 * s; kv = k0 * c - k1 * s; }
    } else {
        qv = row[h * HD_ + d];
        kv = row[HID_ + h * HD_ + d];
    }
    float vv = row[2 * HID_ + h * HD_ + d];
    size_t o = (size_t)t * HID_ + h * HD_ + d;
    q[o] = qv; k[o] = kv; v[o] = vv;
    if (kc) {
        int slot = slots[t];
        size_t co = ((size_t)slot * NH_ + h) * HD_ + d;
        kc[co] = kv; vc[co] = vv;
    }
}

// ---------------- causal softmax (zero-fills above diagonal) ----------------
__global__ void softmax_causal(float* __restrict__ Sc) {
    int row = blockIdx.x;
    int qi = row & (S_ - 1);
    float* sr = Sc + (size_t)row * S_;
    int n = qi + 1;
    int tid = threadIdx.x;
    __shared__ float red[8];

    float m = -1e30f;
    for (int k = tid; k < n; k += 256) m = fmaxf(m, sr[k]);
#pragma unroll
    for (int o = 16; o; o >>= 1) m = fmaxf(m, __shfl_xor_sync(0xffffffffu, m, o));
    if ((tid & 31) == 0) red[tid >> 5] = m;
    __syncthreads();
    float mm = red[0];
#pragma unroll
    for (int i = 1; i < 8; i++) mm = fmaxf(mm, red[i]);
    __syncthreads();

    float sum = 0.f;
    for (int k = tid; k < n; k += 256) {
        float e = expf(sr[k] - mm);
        sr[k] = e;
        sum += e;
    }
#pragma unroll
    for (int o = 16; o; o >>= 1) sum += __shfl_xor_sync(0xffffffffu, sum, o);
    if ((tid & 31) == 0) red[tid >> 5] = sum;
    __syncthreads();
    float tot = 0.f;
#pragma unroll
    for (int i = 0; i < 8; i++) tot += red[i];
    float inv = 1.f / tot;
    for (int k = tid; k < n; k += 256) sr[k] *= inv;
    for (int k = n + tid; k < S_; k += 256) sr[k] = 0.f;
}

// ---------------- silu(gate) * up -> split fp16 planes ----------------
__global__ void silu_mul(const float* __restrict__ gu,
                         __half* __restrict__ acth,
                         __half* __restrict__ actl) {
    size_t idx = (size_t)blockIdx.x * 256 + threadIdx.x;
    size_t t = idx / INTER_;
    size_t i = idx - t * INTER_;
    const float* row = gu + t * (2 * INTER_);
    float g = row[i];
    float u = row[INTER_ + i];
    float y = (g / (1.f + expf(-g))) * u;
    __half h = __float2half_rn(y);
    acth[idx] = h;
    actl[idx] = __float2half_rn(y - __half2float(h));
}

// ---------------- host orchestration ----------------
static void run_w(const __half* Ah, const __half* Al, const float* W,
                  const float* bias, float* C, int M, int K, int N,
                  float* scratch) {
    uint32_t* wh = (uint32_t*)(scratch + OFF_WPH);
    uint32_t* wl = (uint32_t*)(scratch + OFF_WPL);
    pack_w<<<(unsigned)(((size_t)K / 2 * N) / 256), 256>>>(W, wh, wl, N);
    gemm_w<<<dim3(N / 64, M / 128), 256, 2 * WST>>>(Ah, Al, wh, wl, bias, C,
                                                    K, N);
}

extern "C" void kernel_launch(void* const* d_in, const int* in_sizes, int n_in,
                              void* d_out, int out_size) {
    const int* input_ids = (const int*)d_in[0];
    const float* cosp = (const float*)d_in[1];
    const float* sinp = (const float*)d_in[2];
    const int* slots = (const int*)d_in[3];
    const float* embed = (const float*)d_in[6];
    const float* qkv_w = (const float*)d_in[7];
    const float* qkv_b = (const float*)d_in[8];
    const float* dense_w = (const float*)d_in[9];
    const float* gateup_w = (const float*)d_in[10];
    const float* down_w = (const float*)d_in[11];
    const float* ln1_w = (const float*)d_in[12];
    const float* ln2_w = (const float*)d_in[13];
    const float* final_ln_w = (const float*)d_in[14];

    float* out = (float*)d_out;

    float* scratch = nullptr;
    cudaGetSymbolAddress((void**)&scratch, g_scratch);
    float* h_ = scratch + OFF_H;
    float* res_ = scratch + OFF_RES;
    float* q_ = scratch + OFF_Q;
    float* k_ = scratch + OFF_K;
    float* v_ = scratch + OFF_V;
    float* qkv_ = scratch + OFF_QKV;
    float* scores_ = scratch + OFF_SCORES;
    float* gu_ = scratch + OFF_GU;
    __half* normh = (__half*)(scratch + OFF_NORM);
    __half* norml = normh + (size_t)T_ * HID_;
    __half* oh = (__half*)(scratch + OFF_O);
    __half* ol = oh + (size_t)T_ * HID_;
    __half* acth = (__half*)(scratch + OFF_ACT);
    __half* actl = acth + (size_t)T_ * INTER_;
    float* attn_ = scratch + OFF_ATTN;

    const size_t CACHE = (size_t)NBLK_ * BLK_ * NH_ * HD_;
    float* kc_base = out + (size_t)T_ * HID_;
    float* vc_base = kc_base + (size_t)L_ * CACHE;
    bool write_cache =
        (size_t)out_size >= (size_t)T_ * HID_ + 2 * (size_t)L_ * CACHE;
    if (write_cache) {
        cudaMemsetAsync(kc_base, 0, 2 * (size_t)L_ * CACHE * sizeof(float), 0);
    }

    embed_kernel<<<T_, 256>>>(input_ids, embed, h_);

    for (int l = 0; l < L_; l++) {
        const float* qkv_wl = qkv_w + (size_t)l * HID_ * 3 * HID_;
        const float* qkv_bl = qkv_b + (size_t)l * 3 * HID_;
        const float* dense_wl = dense_w + (size_t)l * HID_ * HID_;
        const float* gateup_wl = gateup_w + (size_t)l * HID_ * 2 * INTER_;
        const float* down_wl = down_w + (size_t)l * INTER_ * HID_;

        rmsnorm_kernel<<<T_, 256>>>(h_, (l == 0) ? nullptr : res_,
                                    ln1_w + (size_t)l * HID_, nullptr, normh,
                                    norml, res_);

        run_w(normh, norml, qkv_wl, qkv_bl, qkv_, T_, HID_, 3 * HID_, scratch);

        {
            dim3 grid(T_, NH_);
            rope_scatter<<<grid, 128>>>(qkv_, cosp, sinp, slots, q_, k_, v_,
                                        write_cache ? kc_base + (size_t)l * CACHE : nullptr,
                                        write_cache ? vc_base + (size_t)l * CACHE : nullptr);
        }

        gemm_f16<1><<<dim3(S_ / 128, S_ / 128, B_ * NH_), 256>>>(
            q_, k_, scores_, nullptr, nullptr);

        softmax_causal<<<B_ * NH_ * S_, 256>>>(scores_);

        gemm_f16<2><<<dim3(1, S_ / 128, B_ * NH_), 256>>>(
            scores_, v_, nullptr, oh, ol);

        run_w(oh, ol, dense_wl, nullptr, attn_, T_, HID_, HID_, scratch);

        rmsnorm_kernel<<<T_, 256>>>(attn_, res_, ln2_w + (size_t)l * HID_,
                                    nullptr, normh, norml, res_);

        run_w(normh, norml, gateup_wl, nullptr, gu_, T_, HID_, 2 * INTER_,
              scratch);

        silu_mul<<<(T_ * INTER_) / 256, 256>>>(gu_, acth, actl);

        run_w(acth, actl, down_wl, nullptr, h_, T_, INTER_, HID_, scratch);
    }

    rmsnorm_kernel<<<T_, 256>>>(h_, res_, final_ln_w, out, nullptr, nullptr,
                                nullptr);
}

// round 13
// speedup vs baseline: 1.1241x; 1.1241x over previous
#include <cuda_runtime.h>
#include <cuda_fp16.h>
#include <math.h>
#include <stdint.h>

// ---------------- model constants ----------------
#define L_     2
#define HID_   4096
#define NH_    32
#define HD_    128
#define INTER_ 13696
#define B_     2
#define S_     1024
#define T_     2048
#define NBLK_  160
#define BLK_   16
#define ROT_   64
#define NFREQ_ 32
#define EPS_   1e-5f
#define SCALE_ 0.08838834764831845f

// ---------------- scratch ----------------
#define OFF_H      ((size_t)0)
#define OFF_RES    ((size_t)8388608)
#define OFF_NORM   ((size_t)16777216)   // half planes: normh/norml
#define OFF_Q      ((size_t)25165824)
#define OFF_K      ((size_t)33554432)
#define OFF_V      ((size_t)41943040)
#define OFF_O      ((size_t)50331648)   // half planes: oh/ol
#define OFF_ATTN   ((size_t)58720256)
#define OFF_QKV    ((size_t)67108864)
#define OFF_SCORES ((size_t)92274688)
#define OFF_GU     ((size_t)159383552)
#define OFF_ACT    ((size_t)215482368)  // half planes: acth/actl (exact fit)
#define OFF_WPH    ((size_t)243531776)  // packed weight hi plane (u32 slots)
#define OFF_WPL    (OFF_WPH + (size_t)56098816)
#define SCRATCH_TOTAL (OFF_WPL + (size_t)56098816)

__device__ float g_scratch[SCRATCH_TOTAL];

__device__ __forceinline__ void split2_f16(float x0, float x1,
                                           uint32_t& hi, uint32_t& lo) {
    __half h0 = __float2half_rn(x0);
    __half h1 = __float2half_rn(x1);
    __half l0 = __float2half_rn(x0 - __half2float(h0));
    __half l1 = __float2half_rn(x1 - __half2float(h1));
    hi = (uint32_t)__half_as_ushort(h0) | ((uint32_t)__half_as_ushort(h1) << 16);
    lo = (uint32_t)__half_as_ushort(l0) | ((uint32_t)__half_as_ushort(l1) << 16);
}

__device__ __forceinline__ uint32_t s2u(const void* p) {
    return (uint32_t)__cvta_generic_to_shared(p);
}
#define CP16(dst, src) \
    asm volatile("cp.async.cg.shared.global [%0], [%1], 16;" :: "r"(dst), "l"(src) : "memory")
#define CP_COMMIT() asm volatile("cp.async.commit_group;" ::: "memory")
#define CP_WAIT1() asm volatile("cp.async.wait_group 1;" ::: "memory")
#define CP_WAIT0() asm volatile("cp.async.wait_group 0;" ::: "memory")

#define MMA_F16(ACC, A0, A1, A2, A3, B0, B1)                                   \
    asm volatile(                                                              \
        "mma.sync.aligned.m16n8k16.row.col.f32.f16.f16.f32 "                   \
        "{%0,%1,%2,%3}, {%4,%5,%6,%7}, {%8,%9}, {%0,%1,%2,%3};"                \
        : "+f"((ACC)[0]), "+f"((ACC)[1]), "+f"((ACC)[2]), "+f"((ACC)[3])       \
        : "r"(A0), "r"(A1), "r"(A2), "r"(A3), "r"(B0), "r"(B1))

// ---------------- embedding gather ----------------
__global__ void embed_kernel(const int* __restrict__ ids,
                             const float* __restrict__ E,
                             float* __restrict__ h) {
    int t = blockIdx.x;
    int id = ids[t];
    const float* er = E + (size_t)id * HID_;
    float* hr = h + (size_t)t * HID_;
    for (int i = threadIdx.x; i < HID_; i += 256) hr[i] = er[i];
}

// ---------------- fused (residual-add) RMSNorm; optional split-f16 out ----
__global__ void rmsnorm_kernel(const float* __restrict__ x,
                               const float* __restrict__ resin,
                               const float* __restrict__ w,
                               float* __restrict__ outn,
                               __half* __restrict__ outh,
                               __half* __restrict__ outl,
                               float* __restrict__ resout) {
    int t = blockIdx.x, tid = threadIdx.x;
    const float* xr = x + (size_t)t * HID_;
    const float* rr = resin ? resin + (size_t)t * HID_ : nullptr;

    float v[16];
    float ss = 0.f;
#pragma unroll
    for (int i = 0; i < 16; i++) {
        int c = tid + i * 256;
        float a = xr[c];
        if (rr) a += rr[c];
        v[i] = a;
        ss += a * a;
    }
    __shared__ float red[8];
#pragma unroll
    for (int o = 16; o; o >>= 1) ss += __shfl_xor_sync(0xffffffffu, ss, o);
    if ((tid & 31) == 0) red[tid >> 5] = ss;
    __syncthreads();
    float tot = 0.f;
#pragma unroll
    for (int i = 0; i < 8; i++) tot += red[i];
    float inv = rsqrtf(tot * (1.0f / HID_) + EPS_);
#pragma unroll
    for (int i = 0; i < 16; i++) {
        int c = tid + i * 256;
        size_t o = (size_t)t * HID_ + c;
        if (resout) resout[o] = v[i];
        float y = w[c] * v[i] * inv;
        if (outn) outn[o] = y;
        if (outh) {
            __half h = __float2half_rn(y);
            outh[o] = h;
            outl[o] = __float2half_rn(y - __half2float(h));
        }
    }
}

// ---------------- weight pack: W[K,N] fp32 -> hi/lo u32 planes [K/2][N] ---
__global__ void pack_w(const float* __restrict__ W,
                       uint32_t* __restrict__ Wh, uint32_t* __restrict__ Wl,
                       int N) {
    size_t idx = (size_t)blockIdx.x * 256 + threadIdx.x;
    size_t p = idx / N;
    size_t n = idx - p * N;
    float x0 = W[(2 * p) * N + n];
    float x1 = W[(2 * p + 1) * N + n];
    uint32_t h, l;
    split2_f16(x0, x1, h, l);
    Wh[idx] = h;
    Wl[idx] = l;
}

// ============================================================
// FP16x3 weight GEMM, crossbar-optimized: CTA 128x128 with only
// 4 warps (128 threads), warp tile 64x64 (2x2 grid). 49 FLOP per
// smem byte vs 32.7 at 64x32. 2-stage cp.async pipeline with
// wait_group 1 (proven R9 scheme). B frags loaded upfront (32 u32),
// A frags per-mt. fp32 accumulators (128 regs).
// Stage: AsH 6144 | AsL 6144 | BsH 4352 | BsL 4352 = 20992 B.
// ============================================================
#define WST 20992

__global__ void __launch_bounds__(128) gemm_w(
    const __half* __restrict__ Ah, const __half* __restrict__ Al,
    const uint32_t* __restrict__ Bh, const uint32_t* __restrict__ Bl,
    const float* __restrict__ bias, float* __restrict__ C,
    int K, int N)
{
    extern __shared__ uint8_t sm[];
    int tid = threadIdx.x;
    int lane = tid & 31, warp = tid >> 5;
    int g = lane >> 2, tg = lane & 3;
    int wm = (warp >> 1) * 64, wn = (warp & 1) * 64;
    int m0 = blockIdx.y * 128, n0 = blockIdx.x * 128;

    // fill mapping (128 threads)
    // A: thread t handles row t, both 16B chunks, both planes (4 cp).
    const __half* pah = Ah + (size_t)(m0 + tid) * K;
    const __half* pal = Al + (size_t)(m0 + tid) * K;
    // B: 256 16B-chunks per plane (8 kpair rows x 32 chunks); thread t
    // handles chunks t and t+128 in each plane (4 cp).
    int br0 = tid >> 5;             // 0..3
    int bq0 = tid & 31;             // chunk col
    int br1 = br0 + 4;              // 4..7
    const uint32_t* pb0h = Bh + (size_t)br0 * N + n0 + bq0 * 4;
    const uint32_t* pb0l = Bl + (size_t)br0 * N + n0 + bq0 * 4;
    const uint32_t* pb1h = Bh + (size_t)br1 * N + n0 + bq0 * 4;
    const uint32_t* pb1l = Bl + (size_t)br1 * N + n0 + bq0 * 4;

    auto fill = [&](int stage, int kt) {
        uint8_t* st = sm + stage * WST;
        int k0 = kt * 16;
        uint32_t da = s2u(st + tid * 48);
        CP16(da, pah + k0);
        CP16(da + 16, pah + k0 + 8);
        CP16(da + 6144, pal + k0);
        CP16(da + 6144 + 16, pal + k0 + 8);
        size_t bo = (size_t)(k0 >> 1) * N;
        uint32_t db0 = s2u(st + 12288 + br0 * 544 + bq0 * 16);
        uint32_t db1 = s2u(st + 12288 + br1 * 544 + bq0 * 16);
        CP16(db0, pb0h + bo);
        CP16(db1, pb1h + bo);
        CP16(db0 + 4352, pb0l + bo);
        CP16(db1 + 4352, pb1l + bo);
        CP_COMMIT();
    };

    float acc[4][8][4] = {};

    auto compute = [&](int stage) {
        const uint8_t* AsH = sm + stage * WST;
        const uint8_t* AsL = AsH + 6144;
        const uint8_t* BsH = AsH + 12288;
        const uint8_t* BsL = AsH + 16640;
        uint32_t bh[8][2], bl[8][2];
#pragma unroll
        for (int nt = 0; nt < 8; nt++) {
            int n = wn + nt * 8 + g;
            const uint8_t* pH = BsH + tg * 544 + n * 4;
            const uint8_t* pL = BsL + tg * 544 + n * 4;
            bh[nt][0] = *(const uint32_t*)(pH);
            bh[nt][1] = *(const uint32_t*)(pH + 4 * 544);
            bl[nt][0] = *(const uint32_t*)(pL);
            bl[nt][1] = *(const uint32_t*)(pL + 4 * 544);
        }
#pragma unroll
        for (int mt = 0; mt < 4; mt++) {
            int m = wm + mt * 16 + g;
            const uint8_t* pH = AsH + m * 48 + tg * 4;
            const uint8_t* pL = AsL + m * 48 + tg * 4;
            uint32_t ah0 = *(const uint32_t*)(pH);
            uint32_t ah1 = *(const uint32_t*)(pH + 8 * 48);
            uint32_t ah2 = *(const uint32_t*)(pH + 16);
            uint32_t ah3 = *(const uint32_t*)(pH + 8 * 48 + 16);
            uint32_t al0 = *(const uint32_t*)(pL);
            uint32_t al1 = *(const uint32_t*)(pL + 8 * 48);
            uint32_t al2 = *(const uint32_t*)(pL + 16);
            uint32_t al3 = *(const uint32_t*)(pL + 8 * 48 + 16);
#pragma unroll
            for (int nt = 0; nt < 8; nt++) {
                MMA_F16(acc[mt][nt], ah0, ah1, ah2, ah3, bl[nt][0], bl[nt][1]);
                MMA_F16(acc[mt][nt], al0, al1, al2, al3, bh[nt][0], bh[nt][1]);
                MMA_F16(acc[mt][nt], ah0, ah1, ah2, ah3, bh[nt][0], bh[nt][1]);
            }
        }
    };

    int nk = K / 16;
    fill(0, 0);
    for (int kt = 0; kt < nk; kt++) {
        int buf = kt & 1;
        if (kt + 1 < nk) {
            fill(buf ^ 1, kt + 1);
            CP_WAIT1();
        } else {
            CP_WAIT0();
        }
        __syncthreads();
        compute(buf);
        __syncthreads();
    }

    // ---- epilogue ----
#pragma unroll
    for (int mt = 0; mt < 4; mt++) {
#pragma unroll
        for (int i = 0; i < 2; i++) {
            int r = m0 + wm + mt * 16 + g + i * 8;
#pragma unroll
            for (int nt = 0; nt < 8; nt++) {
                int c = n0 + wn + nt * 8 + 2 * tg;
                float v0 = acc[mt][nt][i * 2 + 0];
                float v1 = acc[mt][nt][i * 2 + 1];
                if (bias) {
                    v0 += bias[c];
                    v1 += bias[c + 1];
                }
                *(float2*)&C[(size_t)r * N + c] = make_float2(v0, v1);
            }
        }
    }
}

// ============================================================
// FP16x3 mma GEMM for attention (proven R9 structure).
// MODE 1: scores = scale * Q @ K^T (fp32 out, causal tile skip).
// MODE 2: O = P @ V, causal K-limit; writes split hi/lo fp16 planes.
// ============================================================
template<int MODE>
__global__ void __launch_bounds__(256) gemm_f16(
    const float* __restrict__ Ag, const float* __restrict__ Bg,
    float* __restrict__ Cf, __half* __restrict__ Ch, __half* __restrict__ Cl)
{
    int bx = blockIdx.x, by = blockIdx.y, bz = blockIdx.z;
    const float* A = Ag;
    const float* B = Bg;
    int K;
    size_t coff;
    if (MODE == 1) {
        if (bx > by) return;
        int b = bz >> 5, h = bz & 31;
        A += ((size_t)b * S_) * HID_ + h * HD_;
        B += ((size_t)b * S_) * HID_ + h * HD_;
        coff = (size_t)bz * S_ * S_;
        K = HD_;
    } else {
        int b = bz >> 5, h = bz & 31;
        A += (size_t)bz * S_ * S_;
        B += ((size_t)b * S_) * HID_ + h * HD_;
        coff = ((size_t)b * S_) * HID_ + h * HD_;
        K = (by + 1) * 128;
    }
    const int lda = (MODE == 1) ? HID_ : S_;
    const int ldb = HID_;

    __shared__ uint8_t AsH[2][6144], AsL[2][6144];
    __shared__ uint8_t BsH[2][6144], BsL[2][6144];

    int tid = threadIdx.x;
    int lane = tid & 31, warp = tid >> 5;
    int g = lane >> 2, tg = lane & 3;
    int wm = (warp & 1) * 64;
    int wn = (warp >> 1) * 32;

    int ar = tid >> 1;
    int ak = (tid & 1) * 8;
    const float* Aptr = A + (size_t)(by * 128 + ar) * lda + ak;

    const float* Bptr0;
    const float* Bptr1 = nullptr;
    int pk = 0, nq = 0;
    if (MODE == 1) {
        Bptr0 = B + (size_t)(bx * 128 + ar) * ldb + ak;
    } else {
        pk = tid >> 5;
        nq = (tid & 31) * 4;
        Bptr0 = B + (size_t)(2 * pk) * ldb + bx * 128 + nq;
        Bptr1 = Bptr0 + ldb;
    }

    float4 pa0, pa1, pb0, pb1;
    auto ldg_tile = [&](int k0) {
        pa0 = *(const float4*)(Aptr + k0);
        pa1 = *(const float4*)(Aptr + k0 + 4);
        if (MODE == 1) {
            pb0 = *(const float4*)(Bptr0 + k0);
            pb1 = *(const float4*)(Bptr0 + k0 + 4);
        } else {
            pb0 = *(const float4*)(Bptr0 + (size_t)k0 * ldb);
            pb1 = *(const float4*)(Bptr1 + (size_t)k0 * ldb);
        }
    };
    auto sts_tile = [&](int buf) {
        uint32_t h0, l0, h1, l1, h2, l2, h3, l3;
        split2_f16(pa0.x, pa0.y, h0, l0);
        split2_f16(pa0.z, pa0.w, h1, l1);
        split2_f16(pa1.x, pa1.y, h2, l2);
        split2_f16(pa1.z, pa1.w, h3, l3);
        *(uint4*)(AsH[buf] + ar * 48 + ak * 2) = make_uint4(h0, h1, h2, h3);
        *(uint4*)(AsL[buf] + ar * 48 + ak * 2) = make_uint4(l0, l1, l2, l3);
        if (MODE == 1) {
            split2_f16(pb0.x, pb0.y, h0, l0);
            split2_f16(pb0.z, pb0.w, h1, l1);
            split2_f16(pb1.x, pb1.y, h2, l2);
            split2_f16(pb1.z, pb1.w, h3, l3);
            *(uint4*)(BsH[buf] + ar * 48 + ak * 2) = make_uint4(h0, h1, h2, h3);
            *(uint4*)(BsL[buf] + ar * 48 + ak * 2) = make_uint4(l0, l1, l2, l3);
        } else {
            split2_f16(pb0.x, pb1.x, h0, l0);
            split2_f16(pb0.y, pb1.y, h1, l1);
            split2_f16(pb0.z, pb1.z, h2, l2);
            split2_f16(pb0.w, pb1.w, h3, l3);
            *(uint4*)(BsH[buf] + pk * 544 + nq * 4) = make_uint4(h0, h1, h2, h3);
            *(uint4*)(BsL[buf] + pk * 544 + nq * 4) = make_uint4(l0, l1, l2, l3);
        }
    };

    float acc[4][4][4] = {};

    auto compute = [&](int buf) {
        uint32_t ah[4][4], al[4][4], bh[4][2], bl[4][2];
#pragma unroll
        for (int mt = 0; mt < 4; mt++) {
            int m = wm + mt * 16 + g;
            const uint8_t* pH = AsH[buf] + m * 48 + tg * 4;
            const uint8_t* pL = AsL[buf] + m * 48 + tg * 4;
            ah[mt][0] = *(const uint32_t*)(pH);
            ah[mt][1] = *(const uint32_t*)(pH + 8 * 48);
            ah[mt][2] = *(const uint32_t*)(pH + 16);
            ah[mt][3] = *(const uint32_t*)(pH + 8 * 48 + 16);
            al[mt][0] = *(const uint32_t*)(pL);
            al[mt][1] = *(const uint32_t*)(pL + 8 * 48);
            al[mt][2] = *(const uint32_t*)(pL + 16);
            al[mt][3] = *(const uint32_t*)(pL + 8 * 48 + 16);
        }
#pragma unroll
        for (int nt = 0; nt < 4; nt++) {
            int n = wn + nt * 8 + g;
            if (MODE == 1) {
                const uint8_t* pH = BsH[buf] + n * 48 + tg * 4;
                const uint8_t* pL = BsL[buf] + n * 48 + tg * 4;
                bh[nt][0] = *(const uint32_t*)(pH);
                bh[nt][1] = *(const uint32_t*)(pH + 16);
                bl[nt][0] = *(const uint32_t*)(pL);
                bl[nt][1] = *(const uint32_t*)(pL + 16);
            } else {
                const uint8_t* pH = BsH[buf] + tg * 544 + n * 4;
                const uint8_t* pL = BsL[buf] + tg * 544 + n * 4;
                bh[nt][0] = *(const uint32_t*)(pH);
                bh[nt][1] = *(const uint32_t*)(pH + 4 * 544);
                bl[nt][0] = *(const uint32_t*)(pL);
                bl[nt][1] = *(const uint32_t*)(pL + 4 * 544);
            }
        }
#pragma unroll
        for (int mt = 0; mt < 4; mt++)
#pragma unroll
            for (int nt = 0; nt < 4; nt++) {
                MMA_F16(acc[mt][nt], ah[mt][0], ah[mt][1], ah[mt][2], ah[mt][3],
                        bl[nt][0], bl[nt][1]);
                MMA_F16(acc[mt][nt], al[mt][0], al[mt][1], al[mt][2], al[mt][3],
                        bh[nt][0], bh[nt][1]);
                MMA_F16(acc[mt][nt], ah[mt][0], ah[mt][1], ah[mt][2], ah[mt][3],
                        bh[nt][0], bh[nt][1]);
            }
    };

    int nk = K / 16;
    ldg_tile(0);
    sts_tile(0);
    __syncthreads();
    for (int kt = 0; kt < nk; kt++) {
        int buf = kt & 1;
        if (kt + 1 < nk) ldg_tile((kt + 1) * 16);
        compute(buf);
        if (kt + 1 < nk) sts_tile(buf ^ 1);
        __syncthreads();
    }

#pragma unroll
    for (int mt = 0; mt < 4; mt++) {
#pragma unroll
        for (int i = 0; i < 2; i++) {
            int r = by * 128 + wm + mt * 16 + g + i * 8;
#pragma unroll
            for (int nt = 0; nt < 4; nt++) {
                int c = bx * 128 + wn + nt * 8 + 2 * tg;
                float v0 = acc[mt][nt][i * 2 + 0];
                float v1 = acc[mt][nt][i * 2 + 1];
                if (MODE == 1) {
                    v0 *= SCALE_;
                    v1 *= SCALE_;
                    *(float2*)&Cf[coff + (size_t)r * S_ + c] =
                        make_float2(v0, v1);
                } else {
                    __half h0 = __float2half_rn(v0);
                    __half h1 = __float2half_rn(v1);
                    __half l0 = __float2half_rn(v0 - __half2float(h0));
                    __half l1 = __float2half_rn(v1 - __half2float(h1));
                    size_t o = coff + (size_t)r * HID_ + c;
                    *(half2*)&Ch[o] = make_half2(h0, h1);
                    *(half2*)&Cl[o] = make_half2(l0, l1);
                }
            }
        }
    }
}

// ---------------- rope + split + KV-cache scatter ----------------
__global__ void rope_scatter(const float* __restrict__ qkv,
                             const float* __restrict__ cosp,
                             const float* __restrict__ sinp,
                             const int* __restrict__ slots,
                             float* __restrict__ q, float* __restrict__ k,
                             float* __restrict__ v,
                             float* __restrict__ kc, float* __restrict__ vc) {
    int t = blockIdx.x, h = blockIdx.y, d = threadIdx.x;
    const float* row = qkv + (size_t)t * (3 * HID_);
    float qv, kv;
    if (d < ROT_) {
        int f = d >> 1;
        float c = cosp[t * NFREQ_ + f];
        float s = sinp[t * NFREQ_ + f];
        float q0 = row[h * HD_ + f * 2];
        float q1 = row[h * HD_ + f * 2 + 1];
        float k0 = row[HID_ + h * HD_ + f * 2];
        float k1 = row[HID_ + h * HD_ + f * 2 + 1];
        if (d & 1) { qv = q1 * c + q0 * s; kv = k1 * c + k0 * s; }
        else       { qv = q0 * c - q1 * s; kv = k0 * c - k1 * s; }
    } else {
        qv = row[h * HD_ + d];
        kv = row[HID_ + h * HD_ + d];
    }
    float vv = row[2 * HID_ + h * HD_ + d];
    size_t o = (size_t)t * HID_ + h * HD_ + d;
    q[o] = qv; k[o] = kv; v[o] = vv;
    if (kc) {
        int slot = slots[t];
        size_t co = ((size_t)slot * NH_ + h) * HD_ + d;
        kc[co] = kv; vc[co] = vv;
    }
}

// ---------------- causal softmax (zero-fills above diagonal) ----------------
__global__ void softmax_causal(float* __restrict__ Sc) {
    int row = blockIdx.x;
    int qi = row & (S_ - 1);
    float* sr = Sc + (size_t)row * S_;
    int n = qi + 1;
    int tid = threadIdx.x;
    __shared__ float red[8];

    float m = -1e30f;
    for (int k = tid; k < n; k += 256) m = fmaxf(m, sr[k]);
#pragma unroll
    for (int o = 16; o; o >>= 1) m = fmaxf(m, __shfl_xor_sync(0xffffffffu, m, o));
    if ((tid & 31) == 0) red[tid >> 5] = m;
    __syncthreads();
    float mm = red[0];
#pragma unroll
    for (int i = 1; i < 8; i++) mm = fmaxf(mm, red[i]);
    __syncthreads();

    float sum = 0.f;
    for (int k = tid; k < n; k += 256) {
        float e = expf(sr[k] - mm);
        sr[k] = e;
        sum += e;
    }
#pragma unroll
    for (int o = 16; o; o >>= 1) sum += __shfl_xor_sync(0xffffffffu, sum, o);
    if ((tid & 31) == 0) red[tid >> 5] = sum;
    __syncthreads();
    float tot = 0.f;
#pragma unroll
    for (int i = 0; i < 8; i++) tot += red[i];
    float inv = 1.f / tot;
    for (int k = tid; k < n; k += 256) sr[k] *= inv;
    for (int k = n + tid; k < S_; k += 256) sr[k] = 0.f;
}

// ---------------- silu(gate) * up -> split fp16 planes ----------------
__global__ void silu_mul(const float* __restrict__ gu,
                         __half* __restrict__ acth,
                         __half* __restrict__ actl) {
    size_t idx = (size_t)blockIdx.x * 256 + threadIdx.x;
    size_t t = idx / INTER_;
    size_t i = idx - t * INTER_;
    const float* row = gu + t * (2 * INTER_);
    float g = row[i];
    float u = row[INTER_ + i];
    float y = (g / (1.f + expf(-g))) * u;
    __half h = __float2half_rn(y);
    acth[idx] = h;
    actl[idx] = __float2half_rn(y - __half2float(h));
}

// ---------------- host orchestration ----------------
static void run_w(const __half* Ah, const __half* Al, const float* W,
                  const float* bias, float* C, int M, int K, int N,
                  float* scratch) {
    uint32_t* wh = (uint32_t*)(scratch + OFF_WPH);
    uint32_t* wl = (uint32_t*)(scratch + OFF_WPL);
    pack_w<<<(unsigned)(((size_t)K / 2 * N) / 256), 256>>>(W, wh, wl, N);
    gemm_w<<<dim3(N / 128, M / 128), 128, 2 * WST>>>(Ah, Al, wh, wl, bias, C,
                                                     K, N);
}

extern "C" void kernel_launch(void* const* d_in, const int* in_sizes, int n_in,
                              void* d_out, int out_size) {
    const int* input_ids = (const int*)d_in[0];
    const float* cosp = (const float*)d_in[1];
    const float* sinp = (const float*)d_in[2];
    const int* slots = (const int*)d_in[3];
    const float* embed = (const float*)d_in[6];
    const float* qkv_w = (const float*)d_in[7];
    const float* qkv_b = (const float*)d_in[8];
    const float* dense_w = (const float*)d_in[9];
    const float* gateup_w = (const float*)d_in[10];
    const float* down_w = (const float*)d_in[11];
    const float* ln1_w = (const float*)d_in[12];
    const float* ln2_w = (const float*)d_in[13];
    const float* final_ln_w = (const float*)d_in[14];

    float* out = (float*)d_out;

    float* scratch = nullptr;
    cudaGetSymbolAddress((void**)&scratch, g_scratch);
    float* h_ = scratch + OFF_H;
    float* res_ = scratch + OFF_RES;
    float* q_ = scratch + OFF_Q;
    float* k_ = scratch + OFF_K;
    float* v_ = scratch + OFF_V;
    float* qkv_ = scratch + OFF_QKV;
    float* scores_ = scratch + OFF_SCORES;
    float* gu_ = scratch + OFF_GU;
    __half* normh = (__half*)(scratch + OFF_NORM);
    __half* norml = normh + (size_t)T_ * HID_;
    __half* oh = (__half*)(scratch + OFF_O);
    __half* ol = oh + (size_t)T_ * HID_;
    __half* acth = (__half*)(scratch + OFF_ACT);
    __half* actl = acth + (size_t)T_ * INTER_;
    float* attn_ = scratch + OFF_ATTN;

    const size_t CACHE = (size_t)NBLK_ * BLK_ * NH_ * HD_;
    float* kc_base = out + (size_t)T_ * HID_;
    float* vc_base = kc_base + (size_t)L_ * CACHE;
    bool write_cache =
        (size_t)out_size >= (size_t)T_ * HID_ + 2 * (size_t)L_ * CACHE;
    if (write_cache) {
        cudaMemsetAsync(kc_base, 0, 2 * (size_t)L_ * CACHE * sizeof(float), 0);
    }

    embed_kernel<<<T_, 256>>>(input_ids, embed, h_);

    for (int l = 0; l < L_; l++) {
        const float* qkv_wl = qkv_w + (size_t)l * HID_ * 3 * HID_;
        const float* qkv_bl = qkv_b + (size_t)l * 3 * HID_;
        const float* dense_wl = dense_w + (size_t)l * HID_ * HID_;
        const float* gateup_wl = gateup_w + (size_t)l * HID_ * 2 * INTER_;
        const float* down_wl = down_w + (size_t)l * INTER_ * HID_;

        rmsnorm_kernel<<<T_, 256>>>(h_, (l == 0) ? nullptr : res_,
                                    ln1_w + (size_t)l * HID_, nullptr, normh,
                                    norml, res_);

        run_w(normh, norml, qkv_wl, qkv_bl, qkv_, T_, HID_, 3 * HID_, scratch);

        {
            dim3 grid(T_, NH_);
            rope_scatter<<<grid, 128>>>(qkv_, cosp, sinp, slots, q_, k_, v_,
                                        write_cache ? kc_base + (size_t)l * CACHE : nullptr,
                                        write_cache ? vc_base + (size_t)l * CACHE : nullptr);
        }

        gemm_f16<1><<<dim3(S_ / 128, S_ / 128, B_ * NH_), 256>>>(
            q_, k_, scores_, nullptr, nullptr);

        softmax_causal<<<B_ * NH_ * S_, 256>>>(scores_);

        gemm_f16<2><<<dim3(1, S_ / 128, B_ * NH_), 256>>>(
            scores_, v_, nullptr, oh, ol);

        run_w(oh, ol, dense_wl, nullptr, attn_, T_, HID_, HID_, scratch);

        rmsnorm_kernel<<<T_, 256>>>(attn_, res_, ln2_w + (size_t)l * HID_,
                                    nullptr, normh, norml, res_);

        run_w(normh, norml, gateup_wl, nullptr, gu_, T_, HID_, 2 * INTER_,
              scratch);

        silu_mul<<<(T_ * INTER_) / 256, 256>>>(gu_, acth, actl);

        run_w(acth, actl, down_wl, nullptr, h_, T_, INTER_, HID_, scratch);
    }

    rmsnorm_kernel<<<T_, 256>>>(h_, res_, final_ln_w, out, nullptr, nullptr,
                                nullptr);
}

// round 14
// speedup vs baseline: 1.2242x; 1.0890x over previous
#include <cuda_runtime.h>
#include <cuda_fp16.h>
#include <math.h>
#include <stdint.h>

// ---------------- model constants ----------------
#define L_     2
#define HID_   4096
#define NH_    32
#define HD_    128
#define INTER_ 13696
#define B_     2
#define S_     1024
#define T_     2048
#define NBLK_  160
#define BLK_   16
#define ROT_   64
#define NFREQ_ 32
#define EPS_   1e-5f
#define SCALE_ 0.08838834764831845f

// ---------------- scratch ----------------
#define OFF_H      ((size_t)0)
#define OFF_RES    ((size_t)8388608)
#define OFF_NORM   ((size_t)16777216)   // half planes: normh/norml
#define OFF_Q      ((size_t)25165824)
#define OFF_K      ((size_t)33554432)
#define OFF_V      ((size_t)41943040)
#define OFF_O      ((size_t)50331648)   // half planes: oh/ol
#define OFF_ATTN   ((size_t)58720256)
#define OFF_QKV    ((size_t)67108864)
#define OFF_SCORES ((size_t)92274688)
#define OFF_GU     ((size_t)159383552)
#define OFF_ACT    ((size_t)215482368)  // half planes: acth/actl (exact fit)
#define OFF_WPH    ((size_t)243531776)  // packed weight hi plane (u32 slots)
#define OFF_WPL    (OFF_WPH + (size_t)56098816)
#define SCRATCH_TOTAL (OFF_WPL + (size_t)56098816)

__device__ float g_scratch[SCRATCH_TOTAL];

__device__ __forceinline__ void split2_f16(float x0, float x1,
                                           uint32_t& hi, uint32_t& lo) {
    __half h0 = __float2half_rn(x0);
    __half h1 = __float2half_rn(x1);
    __half l0 = __float2half_rn(x0 - __half2float(h0));
    __half l1 = __float2half_rn(x1 - __half2float(h1));
    hi = (uint32_t)__half_as_ushort(h0) | ((uint32_t)__half_as_ushort(h1) << 16);
    lo = (uint32_t)__half_as_ushort(l0) | ((uint32_t)__half_as_ushort(l1) << 16);
}

__device__ __forceinline__ uint32_t s2u(const void* p) {
    return (uint32_t)__cvta_generic_to_shared(p);
}
#define CP16(dst, src) \
    asm volatile("cp.async.cg.shared.global [%0], [%1], 16;" :: "r"(dst), "l"(src) : "memory")
#define CP_COMMIT() asm volatile("cp.async.commit_group;" ::: "memory")
#define CP_WAIT1() asm volatile("cp.async.wait_group 1;" ::: "memory")
#define CP_WAIT0() asm volatile("cp.async.wait_group 0;" ::: "memory")

#define MMA_F16(ACC, A0, A1, A2, A3, B0, B1)                                   \
    asm volatile(                                                              \
        "mma.sync.aligned.m16n8k16.row.col.f32.f16.f16.f32 "                   \
        "{%0,%1,%2,%3}, {%4,%5,%6,%7}, {%8,%9}, {%0,%1,%2,%3};"                \
        : "+f"((ACC)[0]), "+f"((ACC)[1]), "+f"((ACC)[2]), "+f"((ACC)[3])       \
        : "r"(A0), "r"(A1), "r"(A2), "r"(A3), "r"(B0), "r"(B1))

#define LDSM4(R, ADDR)                                                         \
    asm volatile(                                                              \
        "ldmatrix.sync.aligned.m8n8.x4.shared.b16 {%0,%1,%2,%3}, [%4];"        \
        : "=r"((R)[0]), "=r"((R)[1]), "=r"((R)[2]), "=r"((R)[3])               \
        : "r"(ADDR))

// ---------------- embedding gather ----------------
__global__ void embed_kernel(const int* __restrict__ ids,
                             const float* __restrict__ E,
                             float* __restrict__ h) {
    int t = blockIdx.x;
    int id = ids[t];
    const float* er = E + (size_t)id * HID_;
    float* hr = h + (size_t)t * HID_;
    for (int i = threadIdx.x; i < HID_; i += 256) hr[i] = er[i];
}

// ---------------- fused (residual-add) RMSNorm; optional split-f16 out ----
__global__ void rmsnorm_kernel(const float* __restrict__ x,
                               const float* __restrict__ resin,
                               const float* __restrict__ w,
                               float* __restrict__ outn,
                               __half* __restrict__ outh,
                               __half* __restrict__ outl,
                               float* __restrict__ resout) {
    int t = blockIdx.x, tid = threadIdx.x;
    const float* xr = x + (size_t)t * HID_;
    const float* rr = resin ? resin + (size_t)t * HID_ : nullptr;

    float v[16];
    float ss = 0.f;
#pragma unroll
    for (int i = 0; i < 16; i++) {
        int c = tid + i * 256;
        float a = xr[c];
        if (rr) a += rr[c];
        v[i] = a;
        ss += a * a;
    }
    __shared__ float red[8];
#pragma unroll
    for (int o = 16; o; o >>= 1) ss += __shfl_xor_sync(0xffffffffu, ss, o);
    if ((tid & 31) == 0) red[tid >> 5] = ss;
    __syncthreads();
    float tot = 0.f;
#pragma unroll
    for (int i = 0; i < 8; i++) tot += red[i];
    float inv = rsqrtf(tot * (1.0f / HID_) + EPS_);
#pragma unroll
    for (int i = 0; i < 16; i++) {
        int c = tid + i * 256;
        size_t o = (size_t)t * HID_ + c;
        if (resout) resout[o] = v[i];
        float y = w[c] * v[i] * inv;
        if (outn) outn[o] = y;
        if (outh) {
            __half h = __float2half_rn(y);
            outh[o] = h;
            outl[o] = __float2half_rn(y - __half2float(h));
        }
    }
}

// ---------------- weight pack: W[K,N] fp32 -> hi/lo u32 planes [K/2][N] ---
__global__ void pack_w(const float* __restrict__ W,
                       uint32_t* __restrict__ Wh, uint32_t* __restrict__ Wl,
                       int N) {
    size_t idx = (size_t)blockIdx.x * 256 + threadIdx.x;
    size_t p = idx / N;
    size_t n = idx - p * N;
    float x0 = W[(2 * p) * N + n];
    float x1 = W[(2 * p + 1) * N + n];
    uint32_t h, l;
    split2_f16(x0, x1, h, l);
    Wh[idx] = h;
    Wl[idx] = l;
}

// ============================================================
// FP16x3 weight GEMM. k-tile 32, 2-stage cp.async pipeline with
// the proven R9 schedule (fill next stage, wait_group 1, 2 syncs).
// A fragments via ldmatrix.x4; B via scalar LDS. CTA 128x128,
// 8 warps x (64x32); 3 passes hi*lo + lo*hi + hi*hi (fp32 acc).
// Stage: AsH 10240 (128x80B) | AsL 10240 | BsH 8704 (16x544B) |
//        BsL 8704 = 37888 B.
// ============================================================
#define WST 37888

__global__ void __launch_bounds__(256, 2) gemm_w(
    const __half* __restrict__ Ah, const __half* __restrict__ Al,
    const uint32_t* __restrict__ Bh, const uint32_t* __restrict__ Bl,
    const float* __restrict__ bias, float* __restrict__ C,
    int K, int N)
{
    extern __shared__ uint8_t sm[];
    int tid = threadIdx.x;
    int lane = tid & 31, warp = tid >> 5;
    int g = lane >> 2, tg = lane & 3;
    int wm = (warp & 1) * 64, wn = (warp >> 1) * 32;
    int m0 = blockIdx.y * 128, n0 = blockIdx.x * 128;

    // fill mapping (from proven R10 k32 fill)
    int fr = tid >> 1;                  // 0..127 (A row)
    int fo = (tid & 1) * 16;            // byte offset (chunks 0/1 of 64B row)
    int foh = (tid & 1) * 8;            // same, in halves
    const __half* pah = Ah + (size_t)(m0 + fr) * K;
    const __half* pal = Al + (size_t)(m0 + fr) * K;
    int bp = tid >> 4;                  // 0..15 (k-pair row)
    int bq = tid & 15;                  // chunk id
    const uint32_t* pbh = Bh + (size_t)bp * N + n0 + bq * 4;
    const uint32_t* pbl = Bl + (size_t)bp * N + n0 + bq * 4;

    auto fill = [&](int stage, int kt) {
        uint8_t* st = sm + stage * WST;
        int k0 = kt * 32;
        uint32_t da = s2u(st + fr * 80 + fo);
        const __half* sa = pah + k0 + foh;
        CP16(da, sa);
        CP16(da + 32, sa + 16);
        const __half* sal = pal + k0 + foh;
        CP16(da + 10240, sal);
        CP16(da + 10240 + 32, sal + 16);
        uint32_t db = s2u(st + 20480 + bp * 544 + bq * 16);
        size_t bo = (size_t)(k0 >> 1) * N;
        CP16(db, pbh + bo);
        CP16(db + 256, pbh + bo + 64);
        CP16(db + 8704, pbl + bo);
        CP16(db + 8704 + 256, pbl + bo + 64);
        CP_COMMIT();
    };

    float acc[4][4][4] = {};

    // per-lane ldmatrix offset within an A plane: row (lane&15), k-half sel
    int aLaneOff = (lane & 15) * 80 + (lane >> 4) * 16;

    auto compute = [&](int stage) {
        uint8_t* base = sm + stage * WST;
        uint32_t aH = s2u(base) + aLaneOff;
        uint32_t aL = aH + 10240;
        const uint8_t* BsH = base + 20480;
        const uint8_t* BsL = base + 29184;
#pragma unroll
        for (int ks = 0; ks < 2; ks++) {
            uint32_t ah[4][4], al[4][4], bh[4][2], bl[4][2];
#pragma unroll
            for (int mt = 0; mt < 4; mt++) {
                uint32_t off = (uint32_t)((wm + mt * 16) * 80 + ks * 32);
                LDSM4(ah[mt], aH + off);
                LDSM4(al[mt], aL + off);
            }
#pragma unroll
            for (int nt = 0; nt < 4; nt++) {
                int n = wn + nt * 8 + g;
                int bo = (ks * 8 + tg) * 544 + n * 4;
                bh[nt][0] = *(const uint32_t*)(BsH + bo);
                bh[nt][1] = *(const uint32_t*)(BsH + bo + 4 * 544);
                bl[nt][0] = *(const uint32_t*)(BsL + bo);
                bl[nt][1] = *(const uint32_t*)(BsL + bo + 4 * 544);
            }
#pragma unroll
            for (int mt = 0; mt < 4; mt++)
#pragma unroll
                for (int nt = 0; nt < 4; nt++) {
                    MMA_F16(acc[mt][nt], ah[mt][0], ah[mt][1], ah[mt][2],
                            ah[mt][3], bl[nt][0], bl[nt][1]);
                    MMA_F16(acc[mt][nt], al[mt][0], al[mt][1], al[mt][2],
                            al[mt][3], bh[nt][0], bh[nt][1]);
                    MMA_F16(acc[mt][nt], ah[mt][0], ah[mt][1], ah[mt][2],
                            ah[mt][3], bh[nt][0], bh[nt][1]);
                }
        }
    };

    int nk = K / 32;
    fill(0, 0);
    for (int kt = 0; kt < nk; kt++) {
        int buf = kt & 1;
        if (kt + 1 < nk) {
            fill(buf ^ 1, kt + 1);
            CP_WAIT1();
        } else {
            CP_WAIT0();
        }
        __syncthreads();
        compute(buf);
        __syncthreads();
    }

    // ---- epilogue ----
#pragma unroll
    for (int mt = 0; mt < 4; mt++) {
#pragma unroll
        for (int i = 0; i < 2; i++) {
            int r = m0 + wm + mt * 16 + g + i * 8;
#pragma unroll
            for (int nt = 0; nt < 4; nt++) {
                int c = n0 + wn + nt * 8 + 2 * tg;
                float v0 = acc[mt][nt][i * 2 + 0];
                float v1 = acc[mt][nt][i * 2 + 1];
                if (bias) {
                    v0 += bias[c];
                    v1 += bias[c + 1];
                }
                *(float2*)&C[(size_t)r * N + c] = make_float2(v0, v1);
            }
        }
    }
}

// ============================================================
// FP16x3 mma GEMM for attention (proven R9 structure).
// MODE 1: scores = scale * Q @ K^T (fp32 out, causal tile skip).
// MODE 2: O = P @ V, causal K-limit; writes split hi/lo fp16 planes.
// ============================================================
template<int MODE>
__global__ void __launch_bounds__(256) gemm_f16(
    const float* __restrict__ Ag, const float* __restrict__ Bg,
    float* __restrict__ Cf, __half* __restrict__ Ch, __half* __restrict__ Cl)
{
    int bx = blockIdx.x, by = blockIdx.y, bz = blockIdx.z;
    const float* A = Ag;
    const float* B = Bg;
    int K;
    size_t coff;
    if (MODE == 1) {
        if (bx > by) return;
        int b = bz >> 5, h = bz & 31;
        A += ((size_t)b * S_) * HID_ + h * HD_;
        B += ((size_t)b * S_) * HID_ + h * HD_;
        coff = (size_t)bz * S_ * S_;
        K = HD_;
    } else {
        int b = bz >> 5, h = bz & 31;
        A += (size_t)bz * S_ * S_;
        B += ((size_t)b * S_) * HID_ + h * HD_;
        coff = ((size_t)b * S_) * HID_ + h * HD_;
        K = (by + 1) * 128;
    }
    const int lda = (MODE == 1) ? HID_ : S_;
    const int ldb = HID_;

    __shared__ uint8_t AsH[2][6144], AsL[2][6144];
    __shared__ uint8_t BsH[2][6144], BsL[2][6144];

    int tid = threadIdx.x;
    int lane = tid & 31, warp = tid >> 5;
    int g = lane >> 2, tg = lane & 3;
    int wm = (warp & 1) * 64;
    int wn = (warp >> 1) * 32;

    int ar = tid >> 1;
    int ak = (tid & 1) * 8;
    const float* Aptr = A + (size_t)(by * 128 + ar) * lda + ak;

    const float* Bptr0;
    const float* Bptr1 = nullptr;
    int pk = 0, nq = 0;
    if (MODE == 1) {
        Bptr0 = B + (size_t)(bx * 128 + ar) * ldb + ak;
    } else {
        pk = tid >> 5;
        nq = (tid & 31) * 4;
        Bptr0 = B + (size_t)(2 * pk) * ldb + bx * 128 + nq;
        Bptr1 = Bptr0 + ldb;
    }

    float4 pa0, pa1, pb0, pb1;
    auto ldg_tile = [&](int k0) {
        pa0 = *(const float4*)(Aptr + k0);
        pa1 = *(const float4*)(Aptr + k0 + 4);
        if (MODE == 1) {
            pb0 = *(const float4*)(Bptr0 + k0);
            pb1 = *(const float4*)(Bptr0 + k0 + 4);
        } else {
            pb0 = *(const float4*)(Bptr0 + (size_t)k0 * ldb);
            pb1 = *(const float4*)(Bptr1 + (size_t)k0 * ldb);
        }
    };
    auto sts_tile = [&](int buf) {
        uint32_t h0, l0, h1, l1, h2, l2, h3, l3;
        split2_f16(pa0.x, pa0.y, h0, l0);
        split2_f16(pa0.z, pa0.w, h1, l1);
        split2_f16(pa1.x, pa1.y, h2, l2);
        split2_f16(pa1.z, pa1.w, h3, l3);
        *(uint4*)(AsH[buf] + ar * 48 + ak * 2) = make_uint4(h0, h1, h2, h3);
        *(uint4*)(AsL[buf] + ar * 48 + ak * 2) = make_uint4(l0, l1, l2, l3);
        if (MODE == 1) {
            split2_f16(pb0.x, pb0.y, h0, l0);
            split2_f16(pb0.z, pb0.w, h1, l1);
            split2_f16(pb1.x, pb1.y, h2, l2);
            split2_f16(pb1.z, pb1.w, h3, l3);
            *(uint4*)(BsH[buf] + ar * 48 + ak * 2) = make_uint4(h0, h1, h2, h3);
            *(uint4*)(BsL[buf] + ar * 48 + ak * 2) = make_uint4(l0, l1, l2, l3);
        } else {
            split2_f16(pb0.x, pb1.x, h0, l0);
            split2_f16(pb0.y, pb1.y, h1, l1);
            split2_f16(pb0.z, pb1.z, h2, l2);
            split2_f16(pb0.w, pb1.w, h3, l3);
            *(uint4*)(BsH[buf] + pk * 544 + nq * 4) = make_uint4(h0, h1, h2, h3);
            *(uint4*)(BsL[buf] + pk * 544 + nq * 4) = make_uint4(l0, l1, l2, l3);
        }
    };

    float acc[4][4][4] = {};

    auto compute = [&](int buf) {
        uint32_t ah[4][4], al[4][4], bh[4][2], bl[4][2];
#pragma unroll
        for (int mt = 0; mt < 4; mt++) {
            int m = wm + mt * 16 + g;
            const uint8_t* pH = AsH[buf] + m * 48 + tg * 4;
            const uint8_t* pL = AsL[buf] + m * 48 + tg * 4;
            ah[mt][0] = *(const uint32_t*)(pH);
            ah[mt][1] = *(const uint32_t*)(pH + 8 * 48);
            ah[mt][2] = *(const uint32_t*)(pH + 16);
            ah[mt][3] = *(const uint32_t*)(pH + 8 * 48 + 16);
            al[mt][0] = *(const uint32_t*)(pL);
            al[mt][1] = *(const uint32_t*)(pL + 8 * 48);
            al[mt][2] = *(const uint32_t*)(pL + 16);
            al[mt][3] = *(const uint32_t*)(pL + 8 * 48 + 16);
        }
#pragma unroll
        for (int nt = 0; nt < 4; nt++) {
            int n = wn + nt * 8 + g;
            if (MODE == 1) {
                const uint8_t* pH = BsH[buf] + n * 48 + tg * 4;
                const uint8_t* pL = BsL[buf] + n * 48 + tg * 4;
                bh[nt][0] = *(const uint32_t*)(pH);
                bh[nt][1] = *(const uint32_t*)(pH + 16);
                bl[nt][0] = *(const uint32_t*)(pL);
                bl[nt][1] = *(const uint32_t*)(pL + 16);
            } else {
                const uint8_t* pH = BsH[buf] + tg * 544 + n * 4;
                const uint8_t* pL = BsL[buf] + tg * 544 + n * 4;
                bh[nt][0] = *(const uint32_t*)(pH);
                bh[nt][1] = *(const uint32_t*)(pH + 4 * 544);
                bl[nt][0] = *(const uint32_t*)(pL);
                bl[nt][1] = *(const uint32_t*)(pL + 4 * 544);
            }
        }
#pragma unroll
        for (int mt = 0; mt < 4; mt++)
#pragma unroll
            for (int nt = 0; nt < 4; nt++) {
                MMA_F16(acc[mt][nt], ah[mt][0], ah[mt][1], ah[mt][2], ah[mt][3],
                        bl[nt][0], bl[nt][1]);
                MMA_F16(acc[mt][nt], al[mt][0], al[mt][1], al[mt][2], al[mt][3],
                        bh[nt][0], bh[nt][1]);
                MMA_F16(acc[mt][nt], ah[mt][0], ah[mt][1], ah[mt][2], ah[mt][3],
                        bh[nt][0], bh[nt][1]);
            }
    };

    int nk = K / 16;
    ldg_tile(0);
    sts_tile(0);
    __syncthreads();
    for (int kt = 0; kt < nk; kt++) {
        int buf = kt & 1;
        if (kt + 1 < nk) ldg_tile((kt + 1) * 16);
        compute(buf);
        if (kt + 1 < nk) sts_tile(buf ^ 1);
        __syncthreads();
    }

#pragma unroll
    for (int mt = 0; mt < 4; mt++) {
#pragma unroll
        for (int i = 0; i < 2; i++) {
            int r = by * 128 + wm + mt * 16 + g + i * 8;
#pragma unroll
            for (int nt = 0; nt < 4; nt++) {
                int c = bx * 128 + wn + nt * 8 + 2 * tg;
                float v0 = acc[mt][nt][i * 2 + 0];
                float v1 = acc[mt][nt][i * 2 + 1];
                if (MODE == 1) {
                    v0 *= SCALE_;
                    v1 *= SCALE_;
                    *(float2*)&Cf[coff + (size_t)r * S_ + c] =
                        make_float2(v0, v1);
                } else {
                    __half h0 = __float2half_rn(v0);
                    __half h1 = __float2half_rn(v1);
                    __half l0 = __float2half_rn(v0 - __half2float(h0));
                    __half l1 = __float2half_rn(v1 - __half2float(h1));
                    size_t o = coff + (size_t)r * HID_ + c;
                    *(half2*)&Ch[o] = make_half2(h0, h1);
                    *(half2*)&Cl[o] = make_half2(l0, l1);
                }
            }
        }
    }
}

// ---------------- rope + split + KV-cache scatter ----------------
__global__ void rope_scatter(const float* __restrict__ qkv,
                             const float* __restrict__ cosp,
                             const float* __restrict__ sinp,
                             const int* __restrict__ slots,
                             float* __restrict__ q, float* __restrict__ k,
                             float* __restrict__ v,
                             float* __restrict__ kc, float* __restrict__ vc) {
    int t = blockIdx.x, h = blockIdx.y, d = threadIdx.x;
    const float* row = qkv + (size_t)t * (3 * HID_);
    float qv, kv;
    if (d < ROT_) {
        int f = d >> 1;
        float c = cosp[t * NFREQ_ + f];
        float s = sinp[t * NFREQ_ + f];
        float q0 = row[h * HD_ + f * 2];
        float q1 = row[h * HD_ + f * 2 + 1];
        float k0 = row[HID_ + h * HD_ + f * 2];
        float k1 = row[HID_ + h * HD_ + f * 2 + 1];
        if (d & 1) { qv = q1 * c + q0 * s; kv = k1 * c + k0 * s; }
        else       { qv = q0 * c - q1 * s; kv = k0 * c - k1 * s; }
    } else {
        qv = row[h * HD_ + d];
        kv = row[HID_ + h * HD_ + d];
    }
    float vv = row[2 * HID_ + h * HD_ + d];
    size_t o = (size_t)t * HID_ + h * HD_ + d;
    q[o] = qv; k[o] = kv; v[o] = vv;
    if (kc) {
        int slot = slots[t];
        size_t co = ((size_t)slot * NH_ + h) * HD_ + d;
        kc[co] = kv; vc[co] = vv;
    }
}

// ---------------- causal softmax (zero-fills above diagonal) ----------------
__global__ void softmax_causal(float* __restrict__ Sc) {
    int row = blockIdx.x;
    int qi = row & (S_ - 1);
    float* sr = Sc + (size_t)row * S_;
    int n = qi + 1;
    int tid = threadIdx.x;
    __shared__ float red[8];

    float m = -1e30f;
    for (int k = tid; k < n; k += 256) m = fmaxf(m, sr[k]);
#pragma unroll
    for (int o = 16; o; o >>= 1) m = fmaxf(m, __shfl_xor_sync(0xffffffffu, m, o));
    if ((tid & 31) == 0) red[tid >> 5] = m;
    __syncthreads();
    float mm = red[0];
#pragma unroll
    for (int i = 1; i < 8; i++) mm = fmaxf(mm, red[i]);
    __syncthreads();

    float sum = 0.f;
    for (int k = tid; k < n; k += 256) {
        float e = expf(sr[k] - mm);
        sr[k] = e;
        sum += e;
    }
#pragma unroll
    for (int o = 16; o; o >>= 1) sum += __shfl_xor_sync(0xffffffffu, sum, o);
    if ((tid & 31) == 0) red[tid >> 5] = sum;
    __syncthreads();
    float tot = 0.f;
#pragma unroll
    for (int i = 0; i < 8; i++) tot += red[i];
    float inv = 1.f / tot;
    for (int k = tid; k < n; k += 256) sr[k] *= inv;
    for (int k = n + tid; k < S_; k += 256) sr[k] = 0.f;
}

// ---------------- silu(gate) * up -> split fp16 planes ----------------
__global__ void silu_mul(const float* __restrict__ gu,
                         __half* __restrict__ acth,
                         __half* __restrict__ actl) {
    size_t idx = (size_t)blockIdx.x * 256 + threadIdx.x;
    size_t t = idx / INTER_;
    size_t i = idx - t * INTER_;
    const float* row = gu + t * (2 * INTER_);
    float g = row[i];
    float u = row[INTER_ + i];
    float y = (g / (1.f + expf(-g))) * u;
    __half h = __float2half_rn(y);
    acth[idx] = h;
    actl[idx] = __float2half_rn(y - __half2float(h));
}

// ---------------- host orchestration ----------------
static void run_w(const __half* Ah, const __half* Al, const float* W,
                  const float* bias, float* C, int M, int K, int N,
                  float* scratch) {
    uint32_t* wh = (uint32_t*)(scratch + OFF_WPH);
    uint32_t* wl = (uint32_t*)(scratch + OFF_WPL);
    pack_w<<<(unsigned)(((size_t)K / 2 * N) / 256), 256>>>(W, wh, wl, N);
    gemm_w<<<dim3(N / 128, M / 128), 256, 2 * WST>>>(Ah, Al, wh, wl, bias, C,
                                                     K, N);
}

extern "C" void kernel_launch(void* const* d_in, const int* in_sizes, int n_in,
                              void* d_out, int out_size) {
    const int* input_ids = (const int*)d_in[0];
    const float* cosp = (const float*)d_in[1];
    const float* sinp = (const float*)d_in[2];
    const int* slots = (const int*)d_in[3];
    const float* embed = (const float*)d_in[6];
    const float* qkv_w = (const float*)d_in[7];
    const float* qkv_b = (const float*)d_in[8];
    const float* dense_w = (const float*)d_in[9];
    const float* gateup_w = (const float*)d_in[10];
    const float* down_w = (const float*)d_in[11];
    const float* ln1_w = (const float*)d_in[12];
    const float* ln2_w = (const float*)d_in[13];
    const float* final_ln_w = (const float*)d_in[14];

    float* out = (float*)d_out;

    // 2 stages x 37888 = 75776 B dynamic smem (> 48KB default): opt in.
    cudaFuncSetAttribute(gemm_w, cudaFuncAttributeMaxDynamicSharedMemorySize,
                         2 * WST);

    float* scratch = nullptr;
    cudaGetSymbolAddress((void**)&scratch, g_scratch);
    float* h_ = scratch + OFF_H;
    float* res_ = scratch + OFF_RES;
    float* q_ = scratch + OFF_Q;
    float* k_ = scratch + OFF_K;
    float* v_ = scratch + OFF_V;
    float* qkv_ = scratch + OFF_QKV;
    float* scores_ = scratch + OFF_SCORES;
    float* gu_ = scratch + OFF_GU;
    __half* normh = (__half*)(scratch + OFF_NORM);
    __half* norml = normh + (size_t)T_ * HID_;
    __half* oh = (__half*)(scratch + OFF_O);
    __half* ol = oh + (size_t)T_ * HID_;
    __half* acth = (__half*)(scratch + OFF_ACT);
    __half* actl = acth + (size_t)T_ * INTER_;
    float* attn_ = scratch + OFF_ATTN;

    const size_t CACHE = (size_t)NBLK_ * BLK_ * NH_ * HD_;
    float* kc_base = out + (size_t)T_ * HID_;
    float* vc_base = kc_base + (size_t)L_ * CACHE;
    bool write_cache =
        (size_t)out_size >= (size_t)T_ * HID_ + 2 * (size_t)L_ * CACHE;
    if (write_cache) {
        cudaMemsetAsync(kc_base, 0, 2 * (size_t)L_ * CACHE * sizeof(float), 0);
    }

    embed_kernel<<<T_, 256>>>(input_ids, embed, h_);

    for (int l = 0; l < L_; l++) {
        const float* qkv_wl = qkv_w + (size_t)l * HID_ * 3 * HID_;
        const float* qkv_bl = qkv_b + (size_t)l * 3 * HID_;
        const float* dense_wl = dense_w + (size_t)l * HID_ * HID_;
        const float* gateup_wl = gateup_w + (size_t)l * HID_ * 2 * INTER_;
        const float* down_wl = down_w + (size_t)l * INTER_ * HID_;

        rmsnorm_kernel<<<T_, 256>>>(h_, (l == 0) ? nullptr : res_,
                                    ln1_w + (size_t)l * HID_, nullptr, normh,
                                    norml, res_);

        run_w(normh, norml, qkv_wl, qkv_bl, qkv_, T_, HID_, 3 * HID_, scratch);

        {
            dim3 grid(T_, NH_);
            rope_scatter<<<grid, 128>>>(qkv_, cosp, sinp, slots, q_, k_, v_,
                                        write_cache ? kc_base + (size_t)l * CACHE : nullptr,
                                        write_cache ? vc_base + (size_t)l * CACHE : nullptr);
        }

        gemm_f16<1><<<dim3(S_ / 128, S_ / 128, B_ * NH_), 256>>>(
            q_, k_, scores_, nullptr, nullptr);

        softmax_causal<<<B_ * NH_ * S_, 256>>>(scores_);

        gemm_f16<2><<<dim3(1, S_ / 128, B_ * NH_), 256>>>(
            scores_, v_, nullptr, oh, ol);

        run_w(oh, ol, dense_wl, nullptr, attn_, T_, HID_, HID_, scratch);

        rmsnorm_kernel<<<T_, 256>>>(attn_, res_, ln2_w + (size_t)l * HID_,
                                    nullptr, normh, norml, res_);

        run_w(normh, norml, gateup_wl, nullptr, gu_, T_, HID_, 2 * INTER_,
              scratch);

        silu_mul<<<(T_ * INTER_) / 256, 256>>>(gu_, acth, actl);

        run_w(acth, actl, down_wl, nullptr, h_, T_, INTER_, HID_, scratch);
    }

    rmsnorm_kernel<<<T_, 256>>>(h_, res_, final_ln_w, out, nullptr, nullptr,
                                nullptr);
}